// round 16
// baseline (speedup 1.0000x reference)
#include <cuda_runtime.h>
#include <cuda_bf16.h>

// Cumulative mean over axis 0 of x[8192, 4096] fp32:
//   out[r, c] = (sum_{i<=r} x[i, c]) / (r + 1)
//
// 3-pass reduce / segmented-scan:
//   pass1_sums : 16-row tile column sums -> g_part (8 MB), batch-8 MLP
//   pass2_seg  : scalar columns; fold 4 partials -> 64-row sums; segmented
//                inclusive scan (8 segs x 16 entries) -> g_s64 + g_segtot
//   pass3_out  : 64-row tiles; excl prefix = g_s64[rt-1] + earlier segment
//                totals; batch-8 streaming scan + scale + __stcs store

#define ROWS   8192
#define COLS   4096
#define C4     (COLS / 4)             // 1024 float4 per row

// ---- pass 1 geometry (T1=16 proven; batch-8 MLP) ----
#define TPB1   256
#define T1     16
#define NT1    (ROWS / T1)            // 512
#define NCB1   (COLS / (TPB1 * 4))    // 4

// ---- 64-row scan geometry ----
#define T3     64
#define NT3    (ROWS / T3)            // 128
#define SEGS   8
#define SEGLEN (NT3 / SEGS)           // 16 entries per segment

// ---- pass 3 geometry ----
#define TPB3   128
#define NCB3   (COLS / (TPB3 * 4))    // 8

// Static device scratch (no allocation allowed anywhere).
__device__ float4 g_part[NT1 * C4];     // 16-row sums, 8 MB
__device__ float  g_s64[NT3 * COLS];    // segment-local inclusive prefixes, 2 MB
__device__ float  g_segtot[SEGS * COLS];// per-segment totals, 128 KB
__device__ float  g_inv[ROWS];          // 1/(r+1)

__device__ __forceinline__ float4 f4_add(float4 a, float4 b) {
    a.x += b.x; a.y += b.y; a.z += b.z; a.w += b.w;
    return a;
}

// ---------------- Pass 1: 16-row tile partial sums (+ inv table) -------------
__global__ void __launch_bounds__(TPB1)
pass1_sums(const float* __restrict__ x) {
    const int bx  = blockIdx.x;
    const int rt  = bx / NCB1;
    const int cb  = bx % NCB1;
    const int tid = threadIdx.x;

    const int gt = bx * TPB1 + tid;
    if (gt < ROWS) g_inv[gt] = 1.0f / (float)(gt + 1);

    const float4* __restrict__ x4 = reinterpret_cast<const float4*>(x);
    const int col4 = cb * TPB1 + tid;
    const int base = rt * T1 * C4 + col4;

    // Two batches of 8 independent LDG.128 (MLP 8), then fold.
    float4 a0 = make_float4(0.f, 0.f, 0.f, 0.f);
    float4 a1 = a0, a2 = a0, a3 = a0;
#pragma unroll
    for (int b = 0; b < T1; b += 8) {
        float4 v0 = __ldg(&x4[base + (b + 0) * C4]);
        float4 v1 = __ldg(&x4[base + (b + 1) * C4]);
        float4 v2 = __ldg(&x4[base + (b + 2) * C4]);
        float4 v3 = __ldg(&x4[base + (b + 3) * C4]);
        float4 v4 = __ldg(&x4[base + (b + 4) * C4]);
        float4 v5 = __ldg(&x4[base + (b + 5) * C4]);
        float4 v6 = __ldg(&x4[base + (b + 6) * C4]);
        float4 v7 = __ldg(&x4[base + (b + 7) * C4]);
        a0 = f4_add(a0, f4_add(v0, v4));
        a1 = f4_add(a1, f4_add(v1, v5));
        a2 = f4_add(a2, f4_add(v2, v6));
        a3 = f4_add(a3, f4_add(v3, v7));
    }
    g_part[rt * C4 + col4] = f4_add(f4_add(a0, a1), f4_add(a2, a3));
}

// ---- Pass 2: segmented scan. 32768 threads (128 blocks): (seg, scalar col). -
__global__ void __launch_bounds__(256)
pass2_seg() {
    const float* gp = reinterpret_cast<const float*>(g_part); // [NT1][COLS]
    const int gt  = blockIdx.x * 256 + threadIdx.x;           // 0..32767
    const int col = gt % COLS;
    const int seg = gt / COLS;                                // 0..7
    const int e0  = seg * SEGLEN;                             // first 64-row entry

    float run = 0.f;
    // 4 batches of 4 entries; each entry = 4 sixteen-row partials.
#pragma unroll
    for (int b = 0; b < SEGLEN; b += 4) {
        float v[16];
#pragma unroll
        for (int j = 0; j < 16; j++)
            v[j] = __ldg(&gp[((e0 + b) * 4 + j) * COLS + col]);  // 16 indep loads
#pragma unroll
        for (int g = 0; g < 4; g++) {
            run += (v[g*4+0] + v[g*4+1]) + (v[g*4+2] + v[g*4+3]);
            g_s64[(e0 + b + g) * COLS + col] = run;       // seg-local inclusive
        }
    }
    g_segtot[seg * COLS + col] = run;
}

// ---------------- Pass 3: streaming final scan + scale + store ---------------
__global__ void __launch_bounds__(TPB3)
pass3_out(const float* __restrict__ x, float* __restrict__ out) {
    const int bx  = blockIdx.x;
    const int rt  = bx / NCB3;            // 64-row tile (0..127)
    const int cb  = bx % NCB3;
    const int tid = threadIdx.x;

    const float4* __restrict__ x4 = reinterpret_cast<const float4*>(x);
    float4*       __restrict__ o4 = reinterpret_cast<float4*>(out);
    const int col4 = cb * TPB3 + tid;
    const int base = rt * T3 * C4 + col4;
    const int row0 = rt * T3;

    // Exclusive prefix = seg-local inclusive of entry rt-1 + earlier seg totals.
    float4 run = make_float4(0.f, 0.f, 0.f, 0.f);
    if (rt > 0) {
        const int e   = rt - 1;
        const int seg = e / SEGLEN;
        run = __ldg(&reinterpret_cast<const float4*>(g_s64)[e * C4 + col4]);
        const float4* st4 = reinterpret_cast<const float4*>(g_segtot);
#pragma unroll
        for (int s = 0; s < SEGS - 1; s++) {
            if (s < seg) run = f4_add(run, __ldg(&st4[s * C4 + col4]));
        }
    }

    // Batch-8: 8 independent loads, then 8 add/scale/store.
#pragma unroll 2
    for (int r = 0; r < T3; r += 8) {
        float4 v[8];
#pragma unroll
        for (int j = 0; j < 8; j++)
            v[j] = __ldg(&x4[base + (r + j) * C4]);

#pragma unroll
        for (int j = 0; j < 8; j++) {
            const float inv = g_inv[row0 + r + j];
            run = f4_add(run, v[j]);
            float4 o;
            o.x = run.x * inv; o.y = run.y * inv;
            o.z = run.z * inv; o.w = run.w * inv;
            __stcs(&o4[base + (r + j) * C4], o);
        }
    }
}

extern "C" void kernel_launch(void* const* d_in, const int* in_sizes, int n_in,
                              void* d_out, int out_size) {
    const float* x   = (const float*)d_in[0];
    float*       out = (float*)d_out;

    pass1_sums<<<NT1 * NCB1, TPB1>>>(x);
    pass2_seg<<<(SEGS * COLS) / 256, 256>>>();
    pass3_out<<<NT3 * NCB3, TPB3>>>(x, out);
}

// round 17
// speedup vs baseline: 1.1002x; 1.1002x over previous
#include <cuda_runtime.h>
#include <cuda_bf16.h>

// Cumulative mean over axis 0 of x[8192, 4096] fp32:
//   out[r, c] = (sum_{i<=r} x[i, c]) / (r + 1)
//
// 3-pass reduce / segmented-scan — best-measured variant of each pass:
//   pass1_sums : 16-row tiles, MLP-4 inner loop        (24.0 us, 5.9 TB/s, R14)
//   pass2_seg  : scalar columns, 8 segs x 16, 128 blks (~3 us, R15/R16)
//   pass3_out  : 64-row tiles, batch-4 interleaved     (~43 us, R14/R15)

#define ROWS   8192
#define COLS   4096
#define C4     (COLS / 4)             // 1024 float4 per row

// ---- pass 1 geometry (proven best: T1=16, MLP-4) ----
#define TPB1   256
#define T1     16
#define NT1    (ROWS / T1)            // 512
#define NCB1   (COLS / (TPB1 * 4))    // 4

// ---- 64-row scan geometry ----
#define T3     64
#define NT3    (ROWS / T3)            // 128
#define SEGS   8
#define SEGLEN (NT3 / SEGS)           // 16 entries per segment

// ---- pass 3 geometry (proven best: TPB=128, batch-4 interleaved) ----
#define TPB3   128
#define NCB3   (COLS / (TPB3 * 4))    // 8

// Static device scratch (no allocation allowed anywhere).
__device__ float4 g_part[NT1 * C4];     // 16-row sums, 8 MB
__device__ float  g_s64[NT3 * COLS];    // segment-local inclusive prefixes, 2 MB
__device__ float  g_segtot[SEGS * COLS];// per-segment totals, 128 KB
__device__ float  g_inv[ROWS];          // 1/(r+1)

__device__ __forceinline__ float4 f4_add(float4 a, float4 b) {
    a.x += b.x; a.y += b.y; a.z += b.z; a.w += b.w;
    return a;
}

// ---------------- Pass 1: 16-row tile partial sums (+ inv table) -------------
__global__ void __launch_bounds__(TPB1)
pass1_sums(const float* __restrict__ x) {
    const int bx  = blockIdx.x;
    const int rt  = bx / NCB1;
    const int cb  = bx % NCB1;
    const int tid = threadIdx.x;

    const int gt = bx * TPB1 + tid;
    if (gt < ROWS) g_inv[gt] = 1.0f / (float)(gt + 1);

    const float4* __restrict__ x4 = reinterpret_cast<const float4*>(x);
    const int col4 = cb * TPB1 + tid;
    const int base = rt * T1 * C4 + col4;

    float4 a0 = make_float4(0.f, 0.f, 0.f, 0.f);
    float4 a1 = a0, a2 = a0, a3 = a0;
#pragma unroll
    for (int r = 0; r < T1; r += 4) {
        float4 v0 = __ldg(&x4[base + (r + 0) * C4]);
        float4 v1 = __ldg(&x4[base + (r + 1) * C4]);
        float4 v2 = __ldg(&x4[base + (r + 2) * C4]);
        float4 v3 = __ldg(&x4[base + (r + 3) * C4]);
        a0 = f4_add(a0, v0);
        a1 = f4_add(a1, v1);
        a2 = f4_add(a2, v2);
        a3 = f4_add(a3, v3);
    }
    g_part[rt * C4 + col4] = f4_add(f4_add(a0, a1), f4_add(a2, a3));
}

// ---- Pass 2: segmented scan. 32768 threads (128 blocks): (seg, scalar col). -
__global__ void __launch_bounds__(256)
pass2_seg() {
    const float* gp = reinterpret_cast<const float*>(g_part); // [NT1][COLS]
    const int gt  = blockIdx.x * 256 + threadIdx.x;           // 0..32767
    const int col = gt % COLS;
    const int seg = gt / COLS;                                // 0..7
    const int e0  = seg * SEGLEN;                             // first 64-row entry

    float run = 0.f;
    // 4 batches of 4 entries; each entry = 4 sixteen-row partials.
#pragma unroll
    for (int b = 0; b < SEGLEN; b += 4) {
        float v[16];
#pragma unroll
        for (int j = 0; j < 16; j++)
            v[j] = __ldg(&gp[((e0 + b) * 4 + j) * COLS + col]);  // 16 indep loads
#pragma unroll
        for (int g = 0; g < 4; g++) {
            run += (v[g*4+0] + v[g*4+1]) + (v[g*4+2] + v[g*4+3]);
            g_s64[(e0 + b + g) * COLS + col] = run;       // seg-local inclusive
        }
    }
    g_segtot[seg * COLS + col] = run;
}

// ---------------- Pass 3: streaming final scan + scale + store ---------------
__global__ void __launch_bounds__(TPB3)
pass3_out(const float* __restrict__ x, float* __restrict__ out) {
    const int bx  = blockIdx.x;
    const int rt  = bx / NCB3;            // 64-row tile (0..127)
    const int cb  = bx % NCB3;
    const int tid = threadIdx.x;

    const float4* __restrict__ x4 = reinterpret_cast<const float4*>(x);
    float4*       __restrict__ o4 = reinterpret_cast<float4*>(out);
    const int col4 = cb * TPB3 + tid;
    const int base = rt * T3 * C4 + col4;
    const int row0 = rt * T3;

    // Exclusive prefix = seg-local inclusive of entry rt-1 + earlier seg totals.
    float4 run = make_float4(0.f, 0.f, 0.f, 0.f);
    if (rt > 0) {
        const int e   = rt - 1;
        const int seg = e / SEGLEN;
        run = __ldg(&reinterpret_cast<const float4*>(g_s64)[e * C4 + col4]);
        const float4* st4 = reinterpret_cast<const float4*>(g_segtot);
#pragma unroll
        for (int s = 0; s < SEGS - 1; s++) {
            if (s < seg) run = f4_add(run, __ldg(&st4[s * C4 + col4]));
        }
    }

    // Batch-4 loads, interleaved add/scale/store (proven best mixed pattern).
#pragma unroll 4
    for (int r = 0; r < T3; r += 4) {
        float4 v0 = __ldg(&x4[base + (r + 0) * C4]);
        float4 v1 = __ldg(&x4[base + (r + 1) * C4]);
        float4 v2 = __ldg(&x4[base + (r + 2) * C4]);
        float4 v3 = __ldg(&x4[base + (r + 3) * C4]);

        const float i0 = g_inv[row0 + r + 0];
        const float i1 = g_inv[row0 + r + 1];
        const float i2 = g_inv[row0 + r + 2];
        const float i3 = g_inv[row0 + r + 3];

        float4 o;
        run = f4_add(run, v0);
        o.x = run.x * i0; o.y = run.y * i0; o.z = run.z * i0; o.w = run.w * i0;
        __stcs(&o4[base + (r + 0) * C4], o);

        run = f4_add(run, v1);
        o.x = run.x * i1; o.y = run.y * i1; o.z = run.z * i1; o.w = run.w * i1;
        __stcs(&o4[base + (r + 1) * C4], o);

        run = f4_add(run, v2);
        o.x = run.x * i2; o.y = run.y * i2; o.z = run.z * i2; o.w = run.w * i2;
        __stcs(&o4[base + (r + 2) * C4], o);

        run = f4_add(run, v3);
        o.x = run.x * i3; o.y = run.y * i3; o.z = run.z * i3; o.w = run.w * i3;
        __stcs(&o4[base + (r + 3) * C4], o);
    }
}

extern "C" void kernel_launch(void* const* d_in, const int* in_sizes, int n_in,
                              void* d_out, int out_size) {
    const float* x   = (const float*)d_in[0];
    float*       out = (float*)d_out;

    pass1_sums<<<NT1 * NCB1, TPB1>>>(x);
    pass2_seg<<<(SEGS * COLS) / 256, 256>>>();
    pass3_out<<<NT3 * NCB3, TPB3>>>(x, out);
}